// round 1
// baseline (speedup 1.0000x reference)
#include <cuda_runtime.h>
#include <cstdint>

// Problem constants
#define BATCH   32
#define HW      56
#define CDIM    384
#define NH      12
#define DH      32
#define WS      7
#define T       49          // WS*WS
#define NWIN    64          // (56/7)^2 per image
#define BN      (BATCH*NWIN)        // 2048 windows total
#define MROWS   (BN*T)              // 100352
#define NQKV    (3*CDIM)            // 1152
#define SCALE   0.17677669529663687f   // 32^-0.5

// Scratch (static device allocations — no cudaMalloc allowed)
// layout: [bn][head][3(q,k,v)][T][DH]
__device__ float g_qkv[(size_t)BN * NH * 3 * T * DH];   // ~462 MB
// layout: [bn*T + t][head*DH + d]  (row-major [M, C])
__device__ float g_att[(size_t)MROWS * CDIM];           // ~154 MB

// ---------------------------------------------------------------------------
// GEMM 1: qkv = gather(x, roll+window) @ Wqkv^T + bqkv
// out scattered into g_qkv [bn][head][which][t][d]
// Tiling: 64x64 output tile, BK=16, 256 threads, 4x4 microtile.
// ---------------------------------------------------------------------------
__global__ __launch_bounds__(256)
void qkv_gemm(const float* __restrict__ x,
              const float* __restrict__ Wqkv,
              const float* __restrict__ bqkv)
{
    __shared__ float As[16][64];
    __shared__ float Bs[16][64];
    __shared__ const float* Arow[64];

    const int tid = threadIdx.x;
    const int mbase = blockIdx.y * 64;
    const int nbase = blockIdx.x * 64;

    if (tid < 64) {
        int row = mbase + tid;
        int bn = row / T, t = row % T;
        int b = bn >> 6, win = bn & 63;
        int wr = win >> 3, wc = win & 7;
        int tr = t / WS, tc = t % WS;
        int h = wr * WS + tr + 3; if (h >= HW) h -= HW;   // roll(-3)
        int w = wc * WS + tc + 3; if (w >= HW) w -= HW;
        Arow[tid] = x + ((size_t)((b * HW + h) * HW + w)) * CDIM;
    }
    __syncthreads();

    float acc[4][4];
    #pragma unroll
    for (int i = 0; i < 4; i++)
        #pragma unroll
        for (int j = 0; j < 4; j++) acc[i][j] = 0.f;

    const int lr  = tid >> 2;   // 0..63 : row within tile (for loading)
    const int lk4 = tid & 3;    // which float4 of the 16-wide k chunk
    const int ty  = tid >> 4;   // 0..15
    const int tx  = tid & 15;   // 0..15

    for (int k0 = 0; k0 < CDIM; k0 += 16) {
        float4 a4 = *(const float4*)(Arow[lr] + k0 + lk4 * 4);
        float4 b4 = *(const float4*)(Wqkv + (size_t)(nbase + lr) * CDIM + k0 + lk4 * 4);
        __syncthreads();   // previous compute done
        As[lk4*4+0][lr] = a4.x; As[lk4*4+1][lr] = a4.y;
        As[lk4*4+2][lr] = a4.z; As[lk4*4+3][lr] = a4.w;
        Bs[lk4*4+0][lr] = b4.x; Bs[lk4*4+1][lr] = b4.y;
        Bs[lk4*4+2][lr] = b4.z; Bs[lk4*4+3][lr] = b4.w;
        __syncthreads();
        #pragma unroll
        for (int k = 0; k < 16; k++) {
            float4 av = *(const float4*)&As[k][ty * 4];
            float4 bv = *(const float4*)&Bs[k][tx * 4];
            float a[4] = {av.x, av.y, av.z, av.w};
            float b[4] = {bv.x, bv.y, bv.z, bv.w};
            #pragma unroll
            for (int i = 0; i < 4; i++)
                #pragma unroll
                for (int j = 0; j < 4; j++)
                    acc[i][j] = fmaf(a[i], b[j], acc[i][j]);
        }
    }

    // Epilogue: add bias, scatter into g_qkv
    #pragma unroll
    for (int i = 0; i < 4; i++) {
        int m = mbase + ty * 4 + i;
        int bn = m / T, t = m % T;
        #pragma unroll
        for (int j = 0; j < 4; j++) {
            int n = nbase + tx * 4 + j;
            float val = acc[i][j] + __ldg(&bqkv[n]);
            int which = n / CDIM;
            int rem   = n - which * CDIM;
            int head  = rem >> 5;       // /32
            int d     = rem & 31;
            size_t addr = ((size_t)(bn * NH + head) * 3 + which) * (T * DH)
                        + t * DH + d;
            g_qkv[addr] = val;
        }
    }
}

// ---------------------------------------------------------------------------
// Attention: one block per (window, head). 49x49 scores, softmax, @V.
// Bias + shifted-window mask computed in-kernel.
// ---------------------------------------------------------------------------
__global__ __launch_bounds__(256)
void attn_kernel(const float* __restrict__ table)
{
    const int bnh  = blockIdx.x;
    const int bn   = bnh / NH;
    const int head = bnh % NH;
    const int tid  = threadIdx.x;

    __shared__ float qs[T * 33];   // stride 33 to avoid bank conflicts
    __shared__ float ks[T * 33];
    __shared__ float vs[T * 33];
    __shared__ float S[T * T];
    __shared__ int   rid[T];

    const float* base = g_qkv + (size_t)(bn * NH + head) * (3 * T * DH);
    for (int i = tid; i < 3 * T * DH; i += blockDim.x) {
        int sec = i / (T * DH);
        int rem = i - sec * (T * DH);
        int t = rem >> 5, d = rem & 31;
        float v = base[i];
        if      (sec == 0) qs[t * 33 + d] = v;
        else if (sec == 1) ks[t * 33 + d] = v;
        else               vs[t * 33 + d] = v;
    }
    if (tid < T) {
        int win = bn & 63;
        int wr = win >> 3, wc = win & 7;
        int tr = tid / WS, tc = tid % WS;
        int h = wr * WS + tr;
        int w = wc * WS + tc;
        int rh = (h < 49) ? 0 : ((h < 53) ? 1 : 2);
        int rw = (w < 49) ? 0 : ((w < 53) ? 1 : 2);
        rid[tid] = rh * 3 + rw;
    }
    __syncthreads();

    // scores + bias + mask
    for (int i = tid; i < T * T; i += blockDim.x) {
        int t = i / T, s = i - t * T;
        float acc = 0.f;
        #pragma unroll
        for (int d = 0; d < DH; d++)
            acc = fmaf(qs[t * 33 + d], ks[s * 33 + d], acc);
        acc *= SCALE;
        int tr = t / WS, tc = t % WS;
        int sr = s / WS, sc = s % WS;
        int idx = (tr - sr + 6) * 13 + (tc - sc + 6);
        acc += __ldg(&table[idx * NH + head]);
        if (rid[t] != rid[s]) acc -= 100.0f;
        S[i] = acc;
    }
    __syncthreads();

    // row softmax (49 threads, one per row)
    if (tid < T) {
        float mx = -1e30f;
        #pragma unroll 7
        for (int s = 0; s < T; s++) mx = fmaxf(mx, S[tid * T + s]);
        float sum = 0.f;
        #pragma unroll 7
        for (int s = 0; s < T; s++) {
            float e = __expf(S[tid * T + s] - mx);
            S[tid * T + s] = e;
            sum += e;
        }
        float inv = 1.0f / sum;
        #pragma unroll 7
        for (int s = 0; s < T; s++) S[tid * T + s] *= inv;
    }
    __syncthreads();

    // P @ V -> g_att
    for (int i = tid; i < T * DH; i += blockDim.x) {
        int t = i >> 5, d = i & 31;
        float acc = 0.f;
        #pragma unroll 7
        for (int s = 0; s < T; s++)
            acc = fmaf(S[t * T + s], vs[s * 33 + d], acc);
        g_att[(size_t)(bn * T + t) * CDIM + head * DH + d] = acc;
    }
}

// ---------------------------------------------------------------------------
// GEMM 2: out = g_att @ Wproj^T + bproj, scattered to [B,56,56,C] w/ roll(+3)
// ---------------------------------------------------------------------------
__global__ __launch_bounds__(256)
void proj_gemm(const float* __restrict__ Wproj,
               const float* __restrict__ bproj,
               float* __restrict__ out)
{
    __shared__ float As[16][64];
    __shared__ float Bs[16][64];

    const int tid = threadIdx.x;
    const int mbase = blockIdx.y * 64;
    const int nbase = blockIdx.x * 64;

    float acc[4][4];
    #pragma unroll
    for (int i = 0; i < 4; i++)
        #pragma unroll
        for (int j = 0; j < 4; j++) acc[i][j] = 0.f;

    const int lr  = tid >> 2;
    const int lk4 = tid & 3;
    const int ty  = tid >> 4;
    const int tx  = tid & 15;

    const float* Abase = g_att + (size_t)(mbase + lr) * CDIM;
    const float* Bbase = Wproj + (size_t)(nbase + lr) * CDIM;

    for (int k0 = 0; k0 < CDIM; k0 += 16) {
        float4 a4 = *(const float4*)(Abase + k0 + lk4 * 4);
        float4 b4 = *(const float4*)(Bbase + k0 + lk4 * 4);
        __syncthreads();
        As[lk4*4+0][lr] = a4.x; As[lk4*4+1][lr] = a4.y;
        As[lk4*4+2][lr] = a4.z; As[lk4*4+3][lr] = a4.w;
        Bs[lk4*4+0][lr] = b4.x; Bs[lk4*4+1][lr] = b4.y;
        Bs[lk4*4+2][lr] = b4.z; Bs[lk4*4+3][lr] = b4.w;
        __syncthreads();
        #pragma unroll
        for (int k = 0; k < 16; k++) {
            float4 av = *(const float4*)&As[k][ty * 4];
            float4 bv = *(const float4*)&Bs[k][tx * 4];
            float a[4] = {av.x, av.y, av.z, av.w};
            float b[4] = {bv.x, bv.y, bv.z, bv.w};
            #pragma unroll
            for (int i = 0; i < 4; i++)
                #pragma unroll
                for (int j = 0; j < 4; j++)
                    acc[i][j] = fmaf(a[i], b[j], acc[i][j]);
        }
    }

    // Epilogue: bias + reverse window partition + roll(+3,+3)
    #pragma unroll
    for (int i = 0; i < 4; i++) {
        int m = mbase + ty * 4 + i;
        int bn = m / T, t = m % T;
        int b = bn >> 6, win = bn & 63;
        int wr = win >> 3, wc = win & 7;
        int tr = t / WS, tc = t % WS;
        int h = wr * WS + tr + 3; if (h >= HW) h -= HW;
        int w = wc * WS + tc + 3; if (w >= HW) w -= HW;
        float* orow = out + ((size_t)((b * HW + h) * HW + w)) * CDIM;
        #pragma unroll
        for (int j = 0; j < 4; j++) {
            int n = nbase + tx * 4 + j;
            orow[n] = acc[i][j] + __ldg(&bproj[n]);
        }
    }
}

// ---------------------------------------------------------------------------
extern "C" void kernel_launch(void* const* d_in, const int* in_sizes, int n_in,
                              void* d_out, int out_size)
{
    const float* x     = (const float*)d_in[0];
    const float* wqkv  = (const float*)d_in[1];
    const float* bqkv  = (const float*)d_in[2];
    const float* wproj = (const float*)d_in[3];
    const float* bproj = (const float*)d_in[4];
    const float* table = (const float*)d_in[5];
    float* out = (float*)d_out;

    dim3 g1(NQKV / 64, MROWS / 64);      // (18, 1568)
    qkv_gemm<<<g1, 256>>>(x, wqkv, bqkv);

    attn_kernel<<<BN * NH, 256>>>(table);  // 24576 blocks

    dim3 g2(CDIM / 64, MROWS / 64);      // (6, 1568)
    proj_gemm<<<g2, 256>>>(wproj, bproj, out);
}

// round 3
// speedup vs baseline: 2.5148x; 2.5148x over previous
#include <cuda_runtime.h>
#include <cuda_bf16.h>
#include <cstdint>

// ---------------- Problem constants ----------------
#define BATCH   32
#define HW      56
#define CDIM    384
#define NH      12
#define DH      32
#define WS      7
#define T       49
#define NWIN    64
#define BN      (BATCH*NWIN)       // 2048
#define MROWS   (BN*T)             // 100352
#define NQKV    (3*CDIM)           // 1152
#define SCALE   0.17677669529663687f

// ---------------- Scratch (static device memory) ----------------
__device__ float          g_qkv[(size_t)BN * NH * 3 * T * DH];     // attn input, fp32
__device__ __nv_bfloat16  g_xw_hi[(size_t)MROWS * CDIM];           // gathered x, hi
__device__ __nv_bfloat16  g_xw_lo[(size_t)MROWS * CDIM];           // gathered x, lo
__device__ __nv_bfloat16  g_att_hi[(size_t)MROWS * CDIM];          // attention out, hi
__device__ __nv_bfloat16  g_att_lo[(size_t)MROWS * CDIM];          // attention out, lo
__device__ __nv_bfloat16  g_wq_hi[(size_t)NQKV * CDIM];
__device__ __nv_bfloat16  g_wq_lo[(size_t)NQKV * CDIM];
__device__ __nv_bfloat16  g_wp_hi[(size_t)CDIM * CDIM];
__device__ __nv_bfloat16  g_wp_lo[(size_t)CDIM * CDIM];

// ---------------- helpers ----------------
__device__ __forceinline__ uint32_t smem_u32(const void* p) {
    uint32_t a;
    asm("{ .reg .u64 t; cvta.to.shared.u64 t, %1; cvt.u32.u64 %0, t; }" : "=r"(a) : "l"(p));
    return a;
}

__device__ __forceinline__ void ldsm_x4(uint32_t& r0, uint32_t& r1, uint32_t& r2, uint32_t& r3,
                                        uint32_t addr) {
    asm volatile("ldmatrix.sync.aligned.m8n8.x4.shared.b16 {%0,%1,%2,%3}, [%4];"
                 : "=r"(r0), "=r"(r1), "=r"(r2), "=r"(r3) : "r"(addr));
}

__device__ __forceinline__ void mma_bf16(float* c, const uint32_t* a, uint32_t b0, uint32_t b1) {
    asm volatile(
        "mma.sync.aligned.m16n8k16.row.col.f32.bf16.bf16.f32 "
        "{%0,%1,%2,%3}, {%4,%5,%6,%7}, {%8,%9}, {%0,%1,%2,%3};"
        : "+f"(c[0]), "+f"(c[1]), "+f"(c[2]), "+f"(c[3])
        : "r"(a[0]), "r"(a[1]), "r"(a[2]), "r"(a[3]), "r"(b0), "r"(b1));
}

__device__ __forceinline__ void split_bf16(float v, __nv_bfloat16& h, __nv_bfloat16& l) {
    h = __float2bfloat16_rn(v);
    l = __float2bfloat16_rn(v - __bfloat162float(h));
}

// ---------------------------------------------------------------------------
// Precompute 1: gather x (roll -3, window partition) -> bf16 hi/lo [MROWS,384]
// ---------------------------------------------------------------------------
__global__ __launch_bounds__(256)
void gather_convert_x(const float* __restrict__ x)
{
    int idx = blockIdx.x * 256 + threadIdx.x;          // one float4 per thread
    if (idx >= MROWS * (CDIM / 4)) return;
    int row = idx / (CDIM / 4);
    int c4  = idx % (CDIM / 4);
    int bn = row / T, t = row % T;
    int b = bn >> 6, win = bn & 63;
    int wr = win >> 3, wc = win & 7;
    int tr = t / WS, tc = t % WS;
    int h = wr * WS + tr + 3; if (h >= HW) h -= HW;
    int w = wc * WS + tc + 3; if (w >= HW) w -= HW;
    float4 v = *(const float4*)(x + ((size_t)((b * HW + h) * HW + w)) * CDIM + c4 * 4);
    __nv_bfloat16 h0,h1,h2,h3,l0,l1,l2,l3;
    split_bf16(v.x,h0,l0); split_bf16(v.y,h1,l1); split_bf16(v.z,h2,l2); split_bf16(v.w,h3,l3);
    size_t o = (size_t)row * CDIM + c4 * 4;
    *(__nv_bfloat162*)(g_xw_hi + o)     = __nv_bfloat162{h0,h1};
    *(__nv_bfloat162*)(g_xw_hi + o + 2) = __nv_bfloat162{h2,h3};
    *(__nv_bfloat162*)(g_xw_lo + o)     = __nv_bfloat162{l0,l1};
    *(__nv_bfloat162*)(g_xw_lo + o + 2) = __nv_bfloat162{l2,l3};
}

// ---------------------------------------------------------------------------
// Precompute 2: fp32 -> bf16 hi/lo (weights)
// ---------------------------------------------------------------------------
__global__ __launch_bounds__(256)
void convert_w(const float* __restrict__ src, __nv_bfloat16* __restrict__ hi,
               __nv_bfloat16* __restrict__ lo, int n4)
{
    int idx = blockIdx.x * 256 + threadIdx.x;
    if (idx >= n4) return;
    float4 v = *(const float4*)(src + (size_t)idx * 4);
    __nv_bfloat16 h0,h1,h2,h3,l0,l1,l2,l3;
    split_bf16(v.x,h0,l0); split_bf16(v.y,h1,l1); split_bf16(v.z,h2,l2); split_bf16(v.w,h3,l3);
    size_t o = (size_t)idx * 4;
    *(__nv_bfloat162*)(hi + o)     = __nv_bfloat162{h0,h1};
    *(__nv_bfloat162*)(hi + o + 2) = __nv_bfloat162{h2,h3};
    *(__nv_bfloat162*)(lo + o)     = __nv_bfloat162{l0,l1};
    *(__nv_bfloat162*)(lo + o + 2) = __nv_bfloat162{l2,l3};
}

// ---------------------------------------------------------------------------
// mma.sync GEMM: C[128,128] = A[128,384] @ B[128,384]^T  (bf16 hi/lo x3)
// 8 warps, warp tile 64x32 (warp grid 2x4), BK=32, padded smem stride 40.
// MODE 0: qkv (A = g_xw, B = g_wq), epilogue scatters fp32 into g_qkv.
// MODE 1: proj (A = g_att, B = g_wp), epilogue scatters to out w/ roll(+3).
// ---------------------------------------------------------------------------
#define SSTR 40   // bf16 elements per smem row (32 data + 8 pad) -> 80B stride

template<int MODE>
__global__ __launch_bounds__(256)
void gemm_mma(const float* __restrict__ bias, float* __restrict__ out)
{
    __shared__ __align__(16) __nv_bfloat16 sAh[128 * SSTR];
    __shared__ __align__(16) __nv_bfloat16 sAl[128 * SSTR];
    __shared__ __align__(16) __nv_bfloat16 sBh[128 * SSTR];
    __shared__ __align__(16) __nv_bfloat16 sBl[128 * SSTR];

    const __nv_bfloat16* __restrict__ a_hi = (MODE == 0) ? g_xw_hi : g_att_hi;
    const __nv_bfloat16* __restrict__ a_lo = (MODE == 0) ? g_xw_lo : g_att_lo;
    const __nv_bfloat16* __restrict__ b_hi = (MODE == 0) ? g_wq_hi : g_wp_hi;
    const __nv_bfloat16* __restrict__ b_lo = (MODE == 0) ? g_wq_lo : g_wp_lo;

    const int tid  = threadIdx.x;
    const int lane = tid & 31;
    const int wid  = tid >> 5;
    const int wm   = wid & 1;        // 0..1  (64 rows each)
    const int wn   = wid >> 1;       // 0..3  (32 cols each)
    const int mbase = blockIdx.y * 128;
    const int nbase = blockIdx.x * 128;

    float acc[4][4][4];
    #pragma unroll
    for (int i = 0; i < 4; i++)
        #pragma unroll
        for (int j = 0; j < 4; j++)
            #pragma unroll
            for (int k = 0; k < 4; k++) acc[i][j][k] = 0.f;

    // ldmatrix base addresses (element offsets; k-step adds 16 elems = 32B)
    const uint32_t uAh = smem_u32(sAh), uAl = smem_u32(sAl);
    const uint32_t uBh = smem_u32(sBh), uBl = smem_u32(sBl);
    const int aRow = wm * 64 + (lane & 15);
    const int aCol = (lane >> 4) << 3;                                   // 0 or 8
    const int bRow = wn * 32 + (lane & 7) + (((lane >> 4) & 1) << 3);    // n within tile
    const int bCol = ((lane >> 3) & 1) << 3;                             // 0 or 8

    // gmem load coords: 512 uint4 per operand tensor, 2 per thread
    const int r0g = (tid + 0)   >> 2, q0g = (tid + 0)   & 3;
    const int r1g = (tid + 256) >> 2, q1g = (tid + 256) & 3;

    for (int k0 = 0; k0 < CDIM; k0 += 32) {
        __syncthreads();   // previous iteration's ldmatrix done
        {
            size_t a0 = (size_t)(mbase + r0g) * CDIM + k0 + q0g * 8;
            size_t a1 = (size_t)(mbase + r1g) * CDIM + k0 + q1g * 8;
            size_t b0 = (size_t)(nbase + r0g) * CDIM + k0 + q0g * 8;
            size_t b1 = (size_t)(nbase + r1g) * CDIM + k0 + q1g * 8;
            int s0 = r0g * SSTR + q0g * 8;
            int s1 = r1g * SSTR + q1g * 8;
            *(uint4*)(sAh + s0) = *(const uint4*)(a_hi + a0);
            *(uint4*)(sAh + s1) = *(const uint4*)(a_hi + a1);
            *(uint4*)(sAl + s0) = *(const uint4*)(a_lo + a0);
            *(uint4*)(sAl + s1) = *(const uint4*)(a_lo + a1);
            *(uint4*)(sBh + s0) = *(const uint4*)(b_hi + b0);
            *(uint4*)(sBh + s1) = *(const uint4*)(b_hi + b1);
            *(uint4*)(sBl + s0) = *(const uint4*)(b_lo + b0);
            *(uint4*)(sBl + s1) = *(const uint4*)(b_lo + b1);
        }
        __syncthreads();

        #pragma unroll
        for (int ks = 0; ks < 2; ks++) {
            const uint32_t kOffB = (uint32_t)((ks * 16) * 2);  // bytes
            uint32_t ah[4][4], al[4][4];
            #pragma unroll
            for (int mt = 0; mt < 4; mt++) {
                uint32_t off = (uint32_t)(((aRow + mt * 16) * SSTR + aCol) * 2) + kOffB;
                ldsm_x4(ah[mt][0], ah[mt][1], ah[mt][2], ah[mt][3], uAh + off);
                ldsm_x4(al[mt][0], al[mt][1], al[mt][2], al[mt][3], uAl + off);
            }
            uint32_t bh[8], bl[8];
            #pragma unroll
            for (int nt2 = 0; nt2 < 2; nt2++) {
                uint32_t off = (uint32_t)(((bRow + nt2 * 16) * SSTR + bCol) * 2) + kOffB;
                ldsm_x4(bh[nt2*4+0], bh[nt2*4+1], bh[nt2*4+2], bh[nt2*4+3], uBh + off);
                ldsm_x4(bl[nt2*4+0], bl[nt2*4+1], bl[nt2*4+2], bl[nt2*4+3], uBl + off);
            }
            #pragma unroll
            for (int mt = 0; mt < 4; mt++)
                #pragma unroll
                for (int nt = 0; nt < 4; nt++) {
                    uint32_t B0h = bh[nt*2+0], B1h = bh[nt*2+1];
                    uint32_t B0l = bl[nt*2+0], B1l = bl[nt*2+1];
                    mma_bf16(acc[mt][nt], ah[mt], B0h, B1h);
                    mma_bf16(acc[mt][nt], ah[mt], B0l, B1l);
                    mma_bf16(acc[mt][nt], al[mt], B0h, B1h);
                }
        }
    }

    // ---- Epilogue ----
    #pragma unroll
    for (int mt = 0; mt < 4; mt++) {
        #pragma unroll
        for (int hf = 0; hf < 2; hf++) {
            int m = mbase + wm * 64 + mt * 16 + (lane >> 2) + hf * 8;
            int bn = m / T, t = m % T;
            if (MODE == 0) {
                #pragma unroll
                for (int nt = 0; nt < 4; nt++) {
                    int col = nbase + wn * 32 + nt * 8 + (lane & 3) * 2;
                    int which = col / CDIM;
                    int rem   = col - which * CDIM;
                    int head  = rem >> 5;
                    int d     = rem & 31;
                    float2 v;
                    v.x = acc[mt][nt][hf*2+0] + __ldg(&bias[col]);
                    v.y = acc[mt][nt][hf*2+1] + __ldg(&bias[col+1]);
                    *(float2*)(g_qkv + ((size_t)(bn * NH + head) * 3 + which) * (T * DH)
                               + t * DH + d) = v;
                }
            } else {
                int b = bn >> 6, win = bn & 63;
                int wr = win >> 3, wc = win & 7;
                int tr = t / WS, tc = t % WS;
                int h = wr * WS + tr + 3; if (h >= HW) h -= HW;
                int w = wc * WS + tc + 3; if (w >= HW) w -= HW;
                float* orow = out + ((size_t)((b * HW + h) * HW + w)) * CDIM;
                #pragma unroll
                for (int nt = 0; nt < 4; nt++) {
                    int col = nbase + wn * 32 + nt * 8 + (lane & 3) * 2;
                    float2 v;
                    v.x = acc[mt][nt][hf*2+0] + __ldg(&bias[col]);
                    v.y = acc[mt][nt][hf*2+1] + __ldg(&bias[col+1]);
                    *(float2*)(orow + col) = v;
                }
            }
        }
    }
}

// ---------------------------------------------------------------------------
// Attention: block per (window, head). Register-tiled 4x4, float4 LDS.
// Output written as bf16 hi/lo for proj GEMM.
// ---------------------------------------------------------------------------
__global__ __launch_bounds__(256)
void attn_kernel(const float* __restrict__ table)
{
    const int bnh  = blockIdx.x;
    const int bn   = bnh / NH;
    const int head = bnh % NH;
    const int tid  = threadIdx.x;

    __shared__ __align__(16) float qT[32 * 52];   // [d][t], t padded to 52
    __shared__ __align__(16) float kT[32 * 52];   // [d][s]
    __shared__ __align__(16) float vs[49 * 32];   // [s][d]
    __shared__ __align__(16) float S[52 * 52];    // [t][s]
    __shared__ int rid[64];

    const float* base = g_qkv + (size_t)(bn * NH + head) * (3 * T * DH);
    for (int i = tid; i < 3 * T * DH; i += 256) {
        int sec = i / (T * DH);
        int rem = i - sec * (T * DH);
        int t = rem >> 5, d = rem & 31;
        float v = base[i];
        if      (sec == 0) qT[d * 52 + t] = v;
        else if (sec == 1) kT[d * 52 + t] = v;
        else               vs[t * 32 + d] = v;
    }
    if (tid < T) {
        int win = bn & 63;
        int wr = win >> 3, wc = win & 7;
        int tr = tid / WS, tc = tid % WS;
        int h = wr * WS + tr;
        int w = wc * WS + tc;
        int rh = (h < 49) ? 0 : ((h < 53) ? 1 : 2);
        int rw = (w < 49) ? 0 : ((w < 53) ? 1 : 2);
        rid[tid] = rh * 3 + rw;
    }
    __syncthreads();

    // ---- S = scale*QK^T + bias + mask ----
    for (int task = tid; task < 169; task += 256) {
        int tb = task / 13, sbk = task % 13;
        float acc[4][4];
        #pragma unroll
        for (int i = 0; i < 4; i++)
            #pragma unroll
            for (int j = 0; j < 4; j++) acc[i][j] = 0.f;
        #pragma unroll
        for (int d = 0; d < 32; d++) {
            float4 qv = *(const float4*)&qT[d * 52 + tb * 4];
            float4 kv = *(const float4*)&kT[d * 52 + sbk * 4];
            float qa[4] = {qv.x, qv.y, qv.z, qv.w};
            float ka[4] = {kv.x, kv.y, kv.z, kv.w};
            #pragma unroll
            for (int i = 0; i < 4; i++)
                #pragma unroll
                for (int j = 0; j < 4; j++)
                    acc[i][j] = fmaf(qa[i], ka[j], acc[i][j]);
        }
        #pragma unroll
        for (int i = 0; i < 4; i++) {
            int t = tb * 4 + i;
            if (t >= T) break;
            int tr = t / WS, tcc = t % WS;
            #pragma unroll
            for (int j = 0; j < 4; j++) {
                int s = sbk * 4 + j;
                if (s >= T) continue;
                int sr = s / WS, sc = s % WS;
                float val = acc[i][j] * SCALE;
                int idx = (tr - sr + 6) * 13 + (tcc - sc + 6);
                val += __ldg(&table[idx * NH + head]);
                if (rid[t] != rid[s]) val -= 100.0f;
                S[t * 52 + s] = val;
            }
        }
    }
    __syncthreads();

    // ---- row softmax ----
    if (tid < T) {
        float mx = -1e30f;
        #pragma unroll 7
        for (int s = 0; s < T; s++) mx = fmaxf(mx, S[tid * 52 + s]);
        float sum = 0.f;
        #pragma unroll 7
        for (int s = 0; s < T; s++) {
            float e = __expf(S[tid * 52 + s] - mx);
            S[tid * 52 + s] = e;
            sum += e;
        }
        float inv = 1.0f / sum;
        #pragma unroll 7
        for (int s = 0; s < T; s++) S[tid * 52 + s] *= inv;
    }
    __syncthreads();

    // ---- out = P @ V, write bf16 hi/lo ----
    for (int task = tid; task < 13 * 8; task += 256) {
        int tb = task / 8, db = task % 8;
        float acc[4][4];
        #pragma unroll
        for (int i = 0; i < 4; i++)
            #pragma unroll
            for (int j = 0; j < 4; j++) acc[i][j] = 0.f;
        for (int s = 0; s < T; s++) {
            float4 vv = *(const float4*)&vs[s * 32 + db * 4];
            float va[4] = {vv.x, vv.y, vv.z, vv.w};
            float p0 = S[(tb * 4 + 0) * 52 + s];
            float p1 = S[(tb * 4 + 1) * 52 + s];
            float p2 = S[(tb * 4 + 2) * 52 + s];
            float p3 = S[(tb * 4 + 3) * 52 + s];
            #pragma unroll
            for (int j = 0; j < 4; j++) {
                acc[0][j] = fmaf(p0, va[j], acc[0][j]);
                acc[1][j] = fmaf(p1, va[j], acc[1][j]);
                acc[2][j] = fmaf(p2, va[j], acc[2][j]);
                acc[3][j] = fmaf(p3, va[j], acc[3][j]);
            }
        }
        #pragma unroll
        for (int i = 0; i < 4; i++) {
            int t = tb * 4 + i;
            if (t >= T) break;
            size_t o = (size_t)(bn * T + t) * CDIM + head * DH + db * 4;
            __nv_bfloat16 h0,h1,h2,h3,l0,l1,l2,l3;
            split_bf16(acc[i][0], h0, l0);
            split_bf16(acc[i][1], h1, l1);
            split_bf16(acc[i][2], h2, l2);
            split_bf16(acc[i][3], h3, l3);
            *(__nv_bfloat162*)(g_att_hi + o)     = __nv_bfloat162{h0,h1};
            *(__nv_bfloat162*)(g_att_hi + o + 2) = __nv_bfloat162{h2,h3};
            *(__nv_bfloat162*)(g_att_lo + o)     = __nv_bfloat162{l0,l1};
            *(__nv_bfloat162*)(g_att_lo + o + 2) = __nv_bfloat162{l2,l3};
        }
    }
}

// ---------------------------------------------------------------------------
extern "C" void kernel_launch(void* const* d_in, const int* in_sizes, int n_in,
                              void* d_out, int out_size)
{
    const float* x     = (const float*)d_in[0];
    const float* wqkv  = (const float*)d_in[1];
    const float* bqkv  = (const float*)d_in[2];
    const float* wproj = (const float*)d_in[3];
    const float* bproj = (const float*)d_in[4];
    const float* table = (const float*)d_in[5];
    float* out = (float*)d_out;

    __nv_bfloat16 *wq_hi, *wq_lo, *wp_hi, *wp_lo;
    cudaGetSymbolAddress((void**)&wq_hi, g_wq_hi);
    cudaGetSymbolAddress((void**)&wq_lo, g_wq_lo);
    cudaGetSymbolAddress((void**)&wp_hi, g_wp_hi);
    cudaGetSymbolAddress((void**)&wp_lo, g_wp_lo);

    // Precompute bf16 hi/lo operands
    gather_convert_x<<<(MROWS * (CDIM/4) + 255) / 256, 256>>>(x);
    convert_w<<<(NQKV * CDIM / 4 + 255) / 256, 256>>>(wqkv,  wq_hi, wq_lo, NQKV * CDIM / 4);
    convert_w<<<(CDIM * CDIM / 4 + 255) / 256, 256>>>(wproj, wp_hi, wp_lo, CDIM * CDIM / 4);

    // QKV GEMM (tensor cores via mma.sync)
    dim3 g1(NQKV / 128, MROWS / 128);     // (9, 784)
    gemm_mma<0><<<g1, 256>>>(bqkv, nullptr);

    // Attention
    attn_kernel<<<BN * NH, 256>>>(table);

    // Projection GEMM
    dim3 g2(CDIM / 128, MROWS / 128);     // (3, 784)
    gemm_mma<1><<<g2, 256>>>(bproj, out);
}